// round 16
// baseline (speedup 1.0000x reference)
#include <cuda_runtime.h>
#include <float.h>

#define TT   3
#define HH   192
#define WW   192
#define CC   64
#define HWSZ (HH*WW)
#define NHC  24
#define NWC  24
#define Q1   (TT*NHC*NWC)   // 1728
#define NHF  48
#define NWF  48
#define QF   (TT*NHF*NWF)   // 6912
#define KK   7
#define SS   192            // candidates per query

// scratch (static __device__ arrays — allowed; no runtime allocation)
__device__ float g_v0t[TT*HWSZ*CC];
__device__ float g_v1t[TT*HWSZ*CC];
__device__ float g_sd[Q1*SS];
__device__ int   g_inds[Q1*KK*3];

__device__ __forceinline__ int refl(int i, int L) {
    i = i < 0 ? -i : i;
    return (i >= L) ? (2*(L-1) - i) : i;
}

// ---------------------------------------------------------------------------
// Transpose (T,C,H,W) -> (T,H,W,C), channels-last, for both videos.
// ---------------------------------------------------------------------------
__global__ void __launch_bounds__(256) transpose_kernel(const float* __restrict__ v0,
                                                        const float* __restrict__ v1) {
    const float* src = (blockIdx.z == 0) ? v0 : v1;
    float* dst       = (blockIdx.z == 0) ? g_v0t : g_v1t;
    const int t    = blockIdx.y;
    const int pix0 = blockIdx.x * 32;

    __shared__ float tile[CC][33];
    const int tx  = threadIdx.x & 31;
    const int grp = threadIdx.x >> 5;   // 0..7

    #pragma unroll
    for (int cc = 0; cc < CC; cc += 8) {
        int c = cc + grp;
        tile[c][tx] = src[((size_t)(t*CC + c))*HWSZ + pix0 + tx];
    }
    __syncthreads();
    #pragma unroll
    for (int i = 0; i < 8; ++i) {
        int idx = i*256 + threadIdx.x;        // 0..2047
        int pix = idx >> 6;                   // 0..31
        int ch  = idx & 63;
        dst[((size_t)t*HWSZ + pix0 + pix)*CC + ch] = tile[ch][pix];
    }
}

// ---------------------------------------------------------------------------
// Stage 1a (R12-exact, best measured 98.4us): 6-query blocks, quad packing,
// fully-unrolled software-pipelined inner loop.
// Per candidate, per offset (dri,ox): p = sequential fma chain over c=0..63,
// then acc += p in (dri major, ox ascending) order. DO NOT REORDER the
// arithmetic — it reproduces the reference's fp tie resolution bit-for-bit.
// ---------------------------------------------------------------------------
#define NQB     6                     // queries per block
#define WCOLS   (8*NQB + 6)           // 54 col slots
#define CSTR2   68                    // col-slot stride (floats)
#define ROWSTR2 (WCOLS*CSTR2 + 12)    // 3684 floats; mod 32 == 4 (conflict-free)
#define SV_BYTES (14*ROWSTR2*4)       // 206304 bytes dynamic smem

#define LOAD_WA(wb, ab, c4)                                                   \
    do {                                                                      \
        _Pragma("unroll")                                                     \
        for (int j = 0; j < 10; ++j)                                          \
            wb[j] = *reinterpret_cast<const float4*>(vrow + j*CSTR2 + (c4)*4);\
        _Pragma("unroll")                                                     \
        for (int ox = 0; ox < 7; ++ox)                                        \
            ab[ox] = *reinterpret_cast<const float4*>(qrow + xq[ox] + (c4)*4);\
    } while (0)

#define COMPUTE_WA(wb, ab)                                                    \
    do {                                                                      \
        _Pragma("unroll")                                                     \
        for (int d = 0; d < 4; ++d) {                                         \
            _Pragma("unroll")                                                 \
            for (int ox = 0; ox < 7; ++ox) {                                  \
                float4 b = wb[d + ox];                                        \
                p[d][ox] = fmaf(ab[ox].x, b.x, p[d][ox]);                     \
                p[d][ox] = fmaf(ab[ox].y, b.y, p[d][ox]);                     \
                p[d][ox] = fmaf(ab[ox].z, b.z, p[d][ox]);                     \
                p[d][ox] = fmaf(ab[ox].w, b.w, p[d][ox]);                     \
            }                                                                 \
        }                                                                     \
    } while (0)

__global__ void __launch_bounds__(288, 1) stage1a_kernel() {
    extern __shared__ float sv[];

    const int qj0 = blockIdx.x * NQB;
    const int qi  = blockIdx.y;
    const int t   = blockIdx.z;
    const int qh  = qi * 8;
    const int qw0 = qj0 * 8;

    const int tid  = threadIdx.x;
    const int slot = tid >> 4;        // 0..17
    const int u    = slot % NQB;      // query within block
    const int qt   = slot / NQB;      // 0..2
    const int sub  = tid & 15;
    const int dyi  = sub >> 1;        // 0..7
    const int quad = sub & 1;         // 0..1 -> dxi base 4*quad

    // cooperative load: candidate window (once)
    const float* v1base = g_v1t + (size_t)t*HWSZ*CC;
    for (int i = tid; i < 14*WCOLS*16; i += 288) {
        int r   = i / (WCOLS*16);
        int rem = i % (WCOLS*16);
        int s   = rem >> 4;
        int c4  = rem & 15;
        int y = refl(qh - 7 + r, HH);
        int x = refl(qw0 - 7 + s, WW);
        float4 v = reinterpret_cast<const float4*>(v1base + ((size_t)y*WW + x)*CC)[c4];
        *reinterpret_cast<float4*>(sv + r*ROWSTR2 + s*CSTR2 + c4*4) = v;
    }
    __syncthreads();

    const int q  = qt*(NHC*NWC) + qi*NWC + (qj0 + u);
    const int qw = qw0 + u*8;

    // query patch col element-offsets (uniform within slot)
    int xq[7];
    #pragma unroll
    for (int ox = 0; ox < 7; ++ox) xq[ox] = refl(qw + ox - 3, WW) * CC;
    const float* v0base = g_v0t + (size_t)qt*HWSZ*CC;

    float acc[4] = {0.f, 0.f, 0.f, 0.f};
    const float* svw = sv + (8*u + 4*quad)*CSTR2;

    for (int dri = 0; dri < 7; ++dri) {
        const int yq = refl(qh + dri - 3, HH);
        const float* qrow = v0base + (size_t)yq*WW*CC;
        const float* vrow = svw + (dyi + dri)*ROWSTR2;

        float p[4][7];
        #pragma unroll
        for (int d = 0; d < 4; ++d)
            #pragma unroll
            for (int ox = 0; ox < 7; ++ox) p[d][ox] = 0.f;

        // software pipeline: prefetch one c4-iter ahead into alternating bufs
        float4 w0[10], a0[7], w1[10], a1[7];
        LOAD_WA(w0, a0, 0);
        #pragma unroll
        for (int c4 = 0; c4 < 16; c4 += 2) {
            LOAD_WA(w1, a1, c4 + 1);     // prefetch c4+1
            COMPUTE_WA(w0, a0);          // compute c4
            if (c4 + 2 < 16)
                LOAD_WA(w0, a0, c4 + 2); // prefetch c4+2
            COMPUTE_WA(w1, a1);          // compute c4+1
        }
        #pragma unroll
        for (int d = 0; d < 4; ++d)
            #pragma unroll
            for (int ox = 0; ox < 7; ++ox) acc[d] += p[d][ox];
    }

    float4 res = make_float4(acc[0], acc[1], acc[2], acc[3]);
    *reinterpret_cast<float4*>(&g_sd[q*SS + t*64 + dyi*8 + 4*quad]) = res;
}

// ---------------------------------------------------------------------------
// Stage 1b: warp-per-query top-7 via shuffles (no block syncs).
// Stable: ties -> lowest candidate index (lax.top_k semantics).
// ---------------------------------------------------------------------------
__global__ void __launch_bounds__(256) stage1b_kernel() {
    const int lane = threadIdx.x & 31;
    const int q = blockIdx.x*8 + (threadIdx.x >> 5);
    const int rr = q % (NHC*NWC);
    const int qh = (rr / NWC) * 8;
    const int qw = (rr % NWC) * 8;

    float v[6];
    #pragma unroll
    for (int j = 0; j < 6; ++j) v[j] = g_sd[q*SS + j*32 + lane];

    #pragma unroll 1
    for (int k = 0; k < KK; ++k) {
        float bv = v[0]; int bi = lane;
        #pragma unroll
        for (int j = 1; j < 6; ++j) {
            if (v[j] > bv) { bv = v[j]; bi = j*32 + lane; }
        }
        #pragma unroll
        for (int s = 16; s > 0; s >>= 1) {
            float ov = __shfl_xor_sync(0xffffffffu, bv, s);
            int   oi = __shfl_xor_sync(0xffffffffu, bi, s);
            if (ov > bv || (ov == bv && oi < bi)) { bv = ov; bi = oi; }
        }
        if (lane == 0) {
            int base = (q*KK + k)*3;
            g_inds[base + 0] = bi >> 6;                   // ct
            g_inds[base + 1] = qh + ((bi >> 3) & 7) - 4;  // ch (raw)
            g_inds[base + 2] = qw + (bi & 7) - 4;         // cw (raw)
        }
        if ((bi & 31) == lane) {
            int jj = bi >> 5;
            #pragma unroll
            for (int j = 0; j < 6; ++j) if (j == jj) v[j] = -FLT_MAX;
        }
    }
}

// ---------------------------------------------------------------------------
// Stage 2+3 fused v7: query patch held in REGISTERS, k-loop inside thread
// (kills the 7x pv re-read — the dominant L1 redundancy).
// block = 4 fine queries x 2 warps = 256 threads (8 warps).
// warp = (qin = w>>1, h = w&1); lane = (par = l>>4, c16 = l&15).
// Lane owns offset class j0 = 2h+par: offsets o = 4i+j0, i = 0..12
// (o >= 49 padded with pv = 0 and offset 0). Per k: 13 x (LDS soff + LDG wv
// + 4 FMA) against register pv, warp reduce, smem partial; 2 warps combined
// at the end. dists_f is tolerance-checked -> summation order free.
// ---------------------------------------------------------------------------
__global__ void __launch_bounds__(256) stage3_kernel(float* __restrict__ out) {
    __shared__ int   scand[4][KK*3];
    __shared__ int   soff[4][KK][52];
    __shared__ float spart[4][KK][2];

    const int tid  = threadIdx.x;
    const int warp = tid >> 5;        // 0..7
    const int qin  = warp >> 1;       // query within block
    const int h    = warp & 1;        // offset half
    const int lane = tid & 31;
    const int par  = lane >> 4;
    const int c16  = lane & 15;
    const int j0   = 2*h + par;       // offset class mod 4

    const int q  = blockIdx.x*4 + qin;
    const int ft = q / (NHF*NWF);
    const int rr = q % (NHF*NWF);
    const int fi = rr / NWF, fj = rr % NWF;
    const int fh = fi*4, fw = fj*4;

    // candidate decode (one warp per query does it) + inds_f output
    if (h == 0 && lane < KK) {
        int it, ih, iw;
        if (lane == 0) { it = ft; ih = fh; iw = fw; }
        else {
            int ci = min(fi >> 1, NHC - 1);
            int cj = min(fj >> 1, NWC - 1);
            int qlin = ft*NHC*NWC + ci*NWC + cj;
            int b = (qlin*KK + lane)*3;
            it = g_inds[b + 0];
            ih = refl(g_inds[b + 1] + (fh - ci*8), HH);
            iw = refl(g_inds[b + 2] + (fw - cj*8), WW);
        }
        scand[qin][lane*3 + 0] = it;
        scand[qin][lane*3 + 1] = ih;
        scand[qin][lane*3 + 2] = iw;
        size_t ob = (size_t)QF*KK + ((size_t)q*KK + lane)*3;
        out[ob + 0] = (float)it;
        out[ob + 1] = (float)ih;
        out[ob + 2] = (float)iw;
    }
    __syncthreads();

    // cooperative offset tables: soff[q][k][j] = (y1*W+x1)*CC, 0 for pads
    for (int i = tid; i < 4*KK*52; i += 256) {
        int qq  = i / (KK*52);
        int rem = i % (KK*52);
        int k = rem / 52, j = rem % 52;
        int v = 0;
        if (j < 49) {
            int y1 = refl(scand[qq][k*3 + 1] + j/7 - 3, HH);
            int x1 = refl(scand[qq][k*3 + 2] + j%7 - 3, WW);
            v = (y1*WW + x1)*CC;
        }
        soff[qq][k][j] = v;
    }

    // register-resident query patch: pv[i] = patch value at o = 4i + j0
    float4 pv[13];
    const float* v0b = g_v0t + (size_t)ft*HWSZ*CC + 4*c16;
    #pragma unroll
    for (int i = 0; i < 13; ++i) {
        int o = 4*i + j0;
        if (o < 49) {
            int y = refl(fh + o/7 - 3, HH);
            int x = refl(fw + o%7 - 3, WW);
            pv[i] = *reinterpret_cast<const float4*>(v0b + ((size_t)y*WW + x)*CC);
        } else {
            pv[i] = make_float4(0.f, 0.f, 0.f, 0.f);
        }
    }
    __syncthreads();

    // mainloop over candidates
    #pragma unroll 1
    for (int k = 0; k < KK; ++k) {
        const int it = scand[qin][k*3 + 0];
        const float* v1b = g_v1t + (size_t)it*HWSZ*CC + 4*c16;
        const int* ms = &soff[qin][k][j0];

        float4 acc = make_float4(0.f, 0.f, 0.f, 0.f);
        #pragma unroll
        for (int i = 0; i < 13; ++i) {
            float4 wv = *reinterpret_cast<const float4*>(v1b + ms[4*i]);
            acc.x = fmaf(pv[i].x, wv.x, acc.x);
            acc.y = fmaf(pv[i].y, wv.y, acc.y);
            acc.z = fmaf(pv[i].z, wv.z, acc.z);
            acc.w = fmaf(pv[i].w, wv.w, acc.w);
        }
        float v = (acc.x + acc.y) + (acc.z + acc.w);
        #pragma unroll
        for (int s = 16; s > 0; s >>= 1)
            v += __shfl_down_sync(0xffffffffu, v, s);
        if (lane == 0)
            spart[qin][k][h] = v;
    }
    __syncthreads();

    // combine the two warp halves
    if (tid < 4*KK) {
        int qq = tid / KK, k = tid % KK;
        out[(size_t)(blockIdx.x*4 + qq)*KK + k] = spart[qq][k][0] + spart[qq][k][1];
    }
}

// ---------------------------------------------------------------------------
extern "C" void kernel_launch(void* const* d_in, const int* in_sizes, int n_in,
                              void* d_out, int out_size) {
    const float* vid0 = (const float*)d_in[0];
    const float* vid1 = (const float*)d_in[1];
    // d_in[2] = flows, unused by the reference

    cudaFuncSetAttribute(stage1a_kernel,
                         cudaFuncAttributeMaxDynamicSharedMemorySize, SV_BYTES);

    dim3 tgrid(HWSZ/32, TT, 2);
    transpose_kernel<<<tgrid, 256>>>(vid0, vid1);
    stage1a_kernel<<<dim3(NWC/NQB, NHC, TT), 288, SV_BYTES>>>();
    stage1b_kernel<<<Q1/8, 256>>>();
    stage3_kernel<<<QF/4, 256>>>((float*)d_out);
}

// round 17
// speedup vs baseline: 1.0312x; 1.0312x over previous
#include <cuda_runtime.h>
#include <float.h>

#define TT   3
#define HH   192
#define WW   192
#define CC   64
#define HWSZ (HH*WW)
#define NHC  24
#define NWC  24
#define Q1   (TT*NHC*NWC)   // 1728
#define NHF  48
#define NWF  48
#define QF   (TT*NHF*NWF)   // 6912
#define KK   7
#define SS   192            // candidates per query

// scratch (static __device__ arrays — allowed; no runtime allocation)
__device__ float g_v0t[TT*HWSZ*CC];
__device__ float g_v1t[TT*HWSZ*CC];
__device__ float g_sd[Q1*SS];
__device__ int   g_inds[Q1*KK*3];

__device__ __forceinline__ int refl(int i, int L) {
    i = i < 0 ? -i : i;
    return (i >= L) ? (2*(L-1) - i) : i;
}

// ---------------------------------------------------------------------------
// Transpose (T,C,H,W) -> (T,H,W,C), channels-last, for both videos.
// ---------------------------------------------------------------------------
__global__ void __launch_bounds__(256) transpose_kernel(const float* __restrict__ v0,
                                                        const float* __restrict__ v1) {
    const float* src = (blockIdx.z == 0) ? v0 : v1;
    float* dst       = (blockIdx.z == 0) ? g_v0t : g_v1t;
    const int t    = blockIdx.y;
    const int pix0 = blockIdx.x * 32;

    __shared__ float tile[CC][33];
    const int tx  = threadIdx.x & 31;
    const int grp = threadIdx.x >> 5;   // 0..7

    #pragma unroll
    for (int cc = 0; cc < CC; cc += 8) {
        int c = cc + grp;
        tile[c][tx] = src[((size_t)(t*CC + c))*HWSZ + pix0 + tx];
    }
    __syncthreads();
    #pragma unroll
    for (int i = 0; i < 8; ++i) {
        int idx = i*256 + threadIdx.x;        // 0..2047
        int pix = idx >> 6;                   // 0..31
        int ch  = idx & 63;
        dst[((size_t)t*HWSZ + pix0 + pix)*CC + ch] = tile[ch][pix];
    }
}

// ---------------------------------------------------------------------------
// Stage 1a (R12-exact, best measured 98.4us): 6-query blocks, quad packing,
// fully-unrolled software-pipelined inner loop.
// Per candidate, per offset (dri,ox): p = sequential fma chain over c=0..63,
// then acc += p in (dri major, ox ascending) order. DO NOT REORDER the
// arithmetic — it reproduces the reference's fp tie resolution bit-for-bit.
// ---------------------------------------------------------------------------
#define NQB     6                     // queries per block
#define WCOLS   (8*NQB + 6)           // 54 col slots
#define CSTR2   68                    // col-slot stride (floats)
#define ROWSTR2 (WCOLS*CSTR2 + 12)    // 3684 floats; mod 32 == 4 (conflict-free)
#define SV_BYTES (14*ROWSTR2*4)       // 206304 bytes dynamic smem

#define LOAD_WA(wb, ab, c4)                                                   \
    do {                                                                      \
        _Pragma("unroll")                                                     \
        for (int j = 0; j < 10; ++j)                                          \
            wb[j] = *reinterpret_cast<const float4*>(vrow + j*CSTR2 + (c4)*4);\
        _Pragma("unroll")                                                     \
        for (int ox = 0; ox < 7; ++ox)                                        \
            ab[ox] = *reinterpret_cast<const float4*>(qrow + xq[ox] + (c4)*4);\
    } while (0)

#define COMPUTE_WA(wb, ab)                                                    \
    do {                                                                      \
        _Pragma("unroll")                                                     \
        for (int d = 0; d < 4; ++d) {                                         \
            _Pragma("unroll")                                                 \
            for (int ox = 0; ox < 7; ++ox) {                                  \
                float4 b = wb[d + ox];                                        \
                p[d][ox] = fmaf(ab[ox].x, b.x, p[d][ox]);                     \
                p[d][ox] = fmaf(ab[ox].y, b.y, p[d][ox]);                     \
                p[d][ox] = fmaf(ab[ox].z, b.z, p[d][ox]);                     \
                p[d][ox] = fmaf(ab[ox].w, b.w, p[d][ox]);                     \
            }                                                                 \
        }                                                                     \
    } while (0)

__global__ void __launch_bounds__(288, 1) stage1a_kernel() {
    extern __shared__ float sv[];

    const int qj0 = blockIdx.x * NQB;
    const int qi  = blockIdx.y;
    const int t   = blockIdx.z;
    const int qh  = qi * 8;
    const int qw0 = qj0 * 8;

    const int tid  = threadIdx.x;
    const int slot = tid >> 4;        // 0..17
    const int u    = slot % NQB;      // query within block
    const int qt   = slot / NQB;      // 0..2
    const int sub  = tid & 15;
    const int dyi  = sub >> 1;        // 0..7
    const int quad = sub & 1;         // 0..1 -> dxi base 4*quad

    // cooperative load: candidate window (once)
    const float* v1base = g_v1t + (size_t)t*HWSZ*CC;
    for (int i = tid; i < 14*WCOLS*16; i += 288) {
        int r   = i / (WCOLS*16);
        int rem = i % (WCOLS*16);
        int s   = rem >> 4;
        int c4  = rem & 15;
        int y = refl(qh - 7 + r, HH);
        int x = refl(qw0 - 7 + s, WW);
        float4 v = reinterpret_cast<const float4*>(v1base + ((size_t)y*WW + x)*CC)[c4];
        *reinterpret_cast<float4*>(sv + r*ROWSTR2 + s*CSTR2 + c4*4) = v;
    }
    __syncthreads();

    const int q  = qt*(NHC*NWC) + qi*NWC + (qj0 + u);
    const int qw = qw0 + u*8;

    // query patch col element-offsets (uniform within slot)
    int xq[7];
    #pragma unroll
    for (int ox = 0; ox < 7; ++ox) xq[ox] = refl(qw + ox - 3, WW) * CC;
    const float* v0base = g_v0t + (size_t)qt*HWSZ*CC;

    float acc[4] = {0.f, 0.f, 0.f, 0.f};
    const float* svw = sv + (8*u + 4*quad)*CSTR2;

    for (int dri = 0; dri < 7; ++dri) {
        const int yq = refl(qh + dri - 3, HH);
        const float* qrow = v0base + (size_t)yq*WW*CC;
        const float* vrow = svw + (dyi + dri)*ROWSTR2;

        float p[4][7];
        #pragma unroll
        for (int d = 0; d < 4; ++d)
            #pragma unroll
            for (int ox = 0; ox < 7; ++ox) p[d][ox] = 0.f;

        // software pipeline: prefetch one c4-iter ahead into alternating bufs
        float4 w0[10], a0[7], w1[10], a1[7];
        LOAD_WA(w0, a0, 0);
        #pragma unroll
        for (int c4 = 0; c4 < 16; c4 += 2) {
            LOAD_WA(w1, a1, c4 + 1);     // prefetch c4+1
            COMPUTE_WA(w0, a0);          // compute c4
            if (c4 + 2 < 16)
                LOAD_WA(w0, a0, c4 + 2); // prefetch c4+2
            COMPUTE_WA(w1, a1);          // compute c4+1
        }
        #pragma unroll
        for (int d = 0; d < 4; ++d)
            #pragma unroll
            for (int ox = 0; ox < 7; ++ox) acc[d] += p[d][ox];
    }

    float4 res = make_float4(acc[0], acc[1], acc[2], acc[3]);
    *reinterpret_cast<float4*>(&g_sd[q*SS + t*64 + dyi*8 + 4*quad]) = res;
}

// ---------------------------------------------------------------------------
// Stage 1b: warp-per-query top-7 via shuffles (no block syncs).
// Stable: ties -> lowest candidate index (lax.top_k semantics).
// ---------------------------------------------------------------------------
__global__ void __launch_bounds__(256) stage1b_kernel() {
    const int lane = threadIdx.x & 31;
    const int q = blockIdx.x*8 + (threadIdx.x >> 5);
    const int rr = q % (NHC*NWC);
    const int qh = (rr / NWC) * 8;
    const int qw = (rr % NWC) * 8;

    float v[6];
    #pragma unroll
    for (int j = 0; j < 6; ++j) v[j] = g_sd[q*SS + j*32 + lane];

    #pragma unroll 1
    for (int k = 0; k < KK; ++k) {
        float bv = v[0]; int bi = lane;
        #pragma unroll
        for (int j = 1; j < 6; ++j) {
            if (v[j] > bv) { bv = v[j]; bi = j*32 + lane; }
        }
        #pragma unroll
        for (int s = 16; s > 0; s >>= 1) {
            float ov = __shfl_xor_sync(0xffffffffu, bv, s);
            int   oi = __shfl_xor_sync(0xffffffffu, bi, s);
            if (ov > bv || (ov == bv && oi < bi)) { bv = ov; bi = oi; }
        }
        if (lane == 0) {
            int base = (q*KK + k)*3;
            g_inds[base + 0] = bi >> 6;                   // ct
            g_inds[base + 1] = qh + ((bi >> 3) & 7) - 4;  // ch (raw)
            g_inds[base + 2] = qw + (bi & 7) - 4;         // cw (raw)
        }
        if ((bi & 31) == lane) {
            int jj = bi >> 5;
            #pragma unroll
            for (int j = 0; j < 6; ++j) if (j == jj) v[j] = -FLT_MAX;
        }
    }
}

// ---------------------------------------------------------------------------
// Stage 2+3 fused v5.2: v5.1 mainloop (occ-88% shape, zero-pixel tail) with
// the prologue slimmed: warp-local candidate decode (shfl broadcast, no scand
// smem), per-warp soff fill (__syncwarp), ONE __syncthreads (for sp only).
// block = 224 threads (7 warps); warp k = candidate k.
// lane: par = lane>>4 (offset parity), c16 = lane&15 (channel quad).
// ---------------------------------------------------------------------------
__global__ void __launch_bounds__(224) stage3_kernel(float* __restrict__ out) {
    const int q  = blockIdx.x;
    const int ft = q / (NHF*NWF);
    const int rr = q % (NHF*NWF);
    const int fi = rr / NWF, fj = rr % NWF;
    const int fh = fi*4, fw = fj*4;

    __shared__ float sp[50*CC];       // 49 patch pixels + 1 zero pixel
    __shared__ int   soff[KK][52];    // per-warp offset tables (pad -> 0)

    const int tid  = threadIdx.x;
    const int warp = tid >> 5;        // = candidate k
    const int lane = tid & 31;

    // cooperative: query patch (vectorized) + zero pixel at o=49
    for (int i = tid; i < 49*16; i += 224) {
        int o = i >> 4, c4 = i & 15;
        int y = refl(fh + (o/7) - 3, HH);
        int x = refl(fw + (o%7) - 3, WW);
        reinterpret_cast<float4*>(sp)[i] =
            reinterpret_cast<const float4*>(g_v0t + ((size_t)ft*HWSZ + (size_t)y*WW + x)*CC)[c4];
    }
    if (tid < 16)
        reinterpret_cast<float4*>(sp)[49*16 + tid] = make_float4(0.f, 0.f, 0.f, 0.f);

    // warp-local candidate decode (lane 0) + shfl broadcast
    int it, ih, iw;
    if (lane == 0) {
        if (warp == 0) { it = ft; ih = fh; iw = fw; }
        else {
            int ci = min(fi >> 1, NHC - 1);
            int cj = min(fj >> 1, NWC - 1);
            int qlin = ft*NHC*NWC + ci*NWC + cj;
            int b = (qlin*KK + warp)*3;
            it = g_inds[b + 0];
            ih = refl(g_inds[b + 1] + (fh - ci*8), HH);
            iw = refl(g_inds[b + 2] + (fw - cj*8), WW);
        }
    }
    it = __shfl_sync(0xffffffffu, it, 0);
    ih = __shfl_sync(0xffffffffu, ih, 0);
    iw = __shfl_sync(0xffffffffu, iw, 0);

    // inds_f (as float), laid out after dists_f — written by lanes 0..2
    if (lane < 3) {
        size_t ob = (size_t)QF*KK + ((size_t)q*KK + warp)*3;
        out[ob + lane] = (float)(lane == 0 ? it : (lane == 1 ? ih : iw));
    }

    // per-warp offset table: soff[warp][j] = (y1*W + x1)*CC, 0 for pads
    #pragma unroll
    for (int j = lane; j < 52; j += 32) {
        int v = 0;
        if (j < 49) {
            int y1 = refl(ih + j/7 - 3, HH);
            int x1 = refl(iw + j%7 - 3, WW);
            v = (y1*WW + x1)*CC;
        }
        soff[warp][j] = v;
    }
    __syncwarp();
    __syncthreads();   // sp ready (soff is warp-local, already visible)

    const int par = lane >> 4;        // offset parity
    const int c16 = lane & 15;        // channel quad
    const float* v1b = g_v1t + (size_t)it*HWSZ*CC + 4*c16;
    const int* mysoff = &soff[warp][par];
    const float* spl = sp + 4*c16;

    float4 acc = make_float4(0.f, 0.f, 0.f, 0.f);
    #pragma unroll 5
    for (int i = 0; i < 25; ++i) {
        int o = 2*i + par;            // par=1,i=24 -> o=49 hits the zero pixel
        float4 wv = *reinterpret_cast<const float4*>(v1b + mysoff[2*i]);
        float4 pv = *reinterpret_cast<const float4*>(spl + o*CC);
        acc.x = fmaf(pv.x, wv.x, acc.x);
        acc.y = fmaf(pv.y, wv.y, acc.y);
        acc.z = fmaf(pv.z, wv.z, acc.z);
        acc.w = fmaf(pv.w, wv.w, acc.w);
    }
    float v = (acc.x + acc.y) + (acc.z + acc.w);
    #pragma unroll
    for (int s = 16; s > 0; s >>= 1)
        v += __shfl_down_sync(0xffffffffu, v, s);
    if (lane == 0)
        out[(size_t)q*KK + warp] = v;
}

// ---------------------------------------------------------------------------
extern "C" void kernel_launch(void* const* d_in, const int* in_sizes, int n_in,
                              void* d_out, int out_size) {
    const float* vid0 = (const float*)d_in[0];
    const float* vid1 = (const float*)d_in[1];
    // d_in[2] = flows, unused by the reference

    cudaFuncSetAttribute(stage1a_kernel,
                         cudaFuncAttributeMaxDynamicSharedMemorySize, SV_BYTES);

    dim3 tgrid(HWSZ/32, TT, 2);
    transpose_kernel<<<tgrid, 256>>>(vid0, vid1);
    stage1a_kernel<<<dim3(NWC/NQB, NHC, TT), 288, SV_BYTES>>>();
    stage1b_kernel<<<Q1/8, 256>>>();
    stage3_kernel<<<QF, 224>>>((float*)d_out);
}